// round 1
// baseline (speedup 1.0000x reference)
#include <cuda_runtime.h>
#include <math.h>

// Problem constants: x[8,2048,1024], W*[1024,1024], bp[1024]
#define BATCH 8
#define SEQ   2048
#define DIM   1024
#define MTOT  (BATCH * SEQ)          // 16384 rows total

// Static device scratch (allocation-free contract):
__device__ float g_Q[(size_t)MTOT * DIM];               // 64 MB
__device__ float g_K[(size_t)MTOT * DIM];               // 64 MB
__device__ float g_V[(size_t)MTOT * DIM];               // 64 MB
__device__ float g_S[(size_t)BATCH * SEQ * SEQ];        // 128 MB
__device__ float g_O[(size_t)MTOT * DIM];               // 64 MB

// ---------------------------------------------------------------------------
// Tiled SGEMM: C = A * B (+bias), optionally B transposed (C = A * B^T).
//   A: [M,K] row-major
//   B: NN -> [K,N] row-major ; NT -> [N,K] row-major
// Tile 128x128x8, 256 threads, 8x8 per thread. All dims are multiples of the
// tile sizes for this problem, so no bounds checks.
// ---------------------------------------------------------------------------
#define BM 128
#define BN 128
#define BK 8
#define TM 8
#define TN 8

template <bool TRANSB, bool BIAS>
__global__ void __launch_bounds__(256)
sgemm_kernel(const float* __restrict__ A,
             const float* __restrict__ B,
             const float* __restrict__ bias,
             float* __restrict__ C,
             int M, int N, int K,
             size_t strideA, size_t strideB, size_t strideC)
{
    A += (size_t)blockIdx.z * strideA;
    B += (size_t)blockIdx.z * strideB;
    C += (size_t)blockIdx.z * strideC;

    __shared__ float As[BK][BM];
    __shared__ float Bs[BK][BN];

    const int tid = threadIdx.x;
    const int tx  = tid & 15;      // 0..15 -> N direction
    const int ty  = tid >> 4;      // 0..15 -> M direction

    const int rowBase = blockIdx.y * BM;
    const int colBase = blockIdx.x * BN;

    // A-tile (and B-tile when TRANSB): 128 rows x 8 cols -> one float4/thread
    const int ldRow = tid >> 1;          // 0..127
    const int ldCol = (tid & 1) * 4;     // 0 or 4
    // B-tile NN: 8 rows x 128 cols -> one float4/thread
    const int bRow = tid >> 5;           // 0..7
    const int bCol = (tid & 31) * 4;     // 0..124

    const float* Aptr = A + (size_t)(rowBase + ldRow) * K + ldCol;
    const float* Bptr = TRANSB
        ? B + (size_t)(colBase + ldRow) * K + ldCol
        : B + (size_t)bRow * N + colBase + bCol;

    float acc[TM][TN];
#pragma unroll
    for (int i = 0; i < TM; i++)
#pragma unroll
        for (int j = 0; j < TN; j++) acc[i][j] = 0.0f;

    for (int k0 = 0; k0 < K; k0 += BK) {
        // Load A tile (transposed into smem)
        float4 av = *reinterpret_cast<const float4*>(Aptr);
        As[ldCol + 0][ldRow] = av.x;
        As[ldCol + 1][ldRow] = av.y;
        As[ldCol + 2][ldRow] = av.z;
        As[ldCol + 3][ldRow] = av.w;

        // Load B tile
        if (TRANSB) {
            float4 bv = *reinterpret_cast<const float4*>(Bptr);
            Bs[ldCol + 0][ldRow] = bv.x;
            Bs[ldCol + 1][ldRow] = bv.y;
            Bs[ldCol + 2][ldRow] = bv.z;
            Bs[ldCol + 3][ldRow] = bv.w;
        } else {
            float4 bv = *reinterpret_cast<const float4*>(Bptr);
            *reinterpret_cast<float4*>(&Bs[bRow][bCol]) = bv;
        }
        __syncthreads();

#pragma unroll
        for (int kk = 0; kk < BK; kk++) {
            float af[TM], bf[TN];
#pragma unroll
            for (int i = 0; i < TM; i++) af[i] = As[kk][ty * TM + i];
#pragma unroll
            for (int j = 0; j < TN; j++) bf[j] = Bs[kk][tx * TN + j];
#pragma unroll
            for (int i = 0; i < TM; i++)
#pragma unroll
                for (int j = 0; j < TN; j++)
                    acc[i][j] = fmaf(af[i], bf[j], acc[i][j]);
        }
        __syncthreads();

        Aptr += BK;
        if (TRANSB) Bptr += BK;
        else        Bptr += (size_t)BK * N;
    }

    // Epilogue
#pragma unroll
    for (int i = 0; i < TM; i++) {
        const int r = rowBase + ty * TM + i;
#pragma unroll
        for (int j = 0; j < TN; j += 4) {
            const int c = colBase + tx * TN + j;
            float4 v = make_float4(acc[i][j], acc[i][j + 1],
                                   acc[i][j + 2], acc[i][j + 3]);
            if (BIAS) {
                v.x += bias[c + 0];
                v.y += bias[c + 1];
                v.z += bias[c + 2];
                v.w += bias[c + 3];
            }
            *reinterpret_cast<float4*>(&C[(size_t)r * N + c]) = v;
        }
    }
}

// ---------------------------------------------------------------------------
// Row softmax over SEQ=2048 elements, with scale applied before max-subtract.
// One block of 256 threads per row; 8 elements per thread.
// ---------------------------------------------------------------------------
__global__ void __launch_bounds__(256)
softmax_rows_kernel(float* __restrict__ S, float scale)
{
    float* p = S + (size_t)blockIdx.x * SEQ;
    const int tid = threadIdx.x;

    float vals[8];
    float lmax = -INFINITY;
#pragma unroll
    for (int i = 0; i < 8; i++) {
        float v = p[tid + i * 256] * scale;
        vals[i] = v;
        lmax = fmaxf(lmax, v);
    }

    __shared__ float red[8];
    // warp-level max
#pragma unroll
    for (int o = 16; o > 0; o >>= 1)
        lmax = fmaxf(lmax, __shfl_xor_sync(0xffffffffu, lmax, o));
    if ((tid & 31) == 0) red[tid >> 5] = lmax;
    __syncthreads();
    float m = red[0];
#pragma unroll
    for (int w = 1; w < 8; w++) m = fmaxf(m, red[w]);
    __syncthreads();

    float lsum = 0.0f;
#pragma unroll
    for (int i = 0; i < 8; i++) {
        vals[i] = expf(vals[i] - m);
        lsum += vals[i];
    }
#pragma unroll
    for (int o = 16; o > 0; o >>= 1)
        lsum += __shfl_xor_sync(0xffffffffu, lsum, o);
    if ((tid & 31) == 0) red[tid >> 5] = lsum;
    __syncthreads();
    float tot = 0.0f;
#pragma unroll
    for (int w = 0; w < 8; w++) tot += red[w];
    const float rinv = 1.0f / tot;

#pragma unroll
    for (int i = 0; i < 8; i++)
        p[tid + i * 256] = vals[i] * rinv;
}

// ---------------------------------------------------------------------------
// kernel_launch
// inputs: x[8,2048,1024], Wq[1024,1024], Wk, Wv, Wp, bp[1024]; out fp32 same as x
// ---------------------------------------------------------------------------
extern "C" void kernel_launch(void* const* d_in, const int* in_sizes, int n_in,
                              void* d_out, int out_size)
{
    (void)in_sizes; (void)n_in; (void)out_size;
    const float* x  = (const float*)d_in[0];
    const float* Wq = (const float*)d_in[1];
    const float* Wk = (const float*)d_in[2];
    const float* Wv = (const float*)d_in[3];
    const float* Wp = (const float*)d_in[4];
    const float* bp = (const float*)d_in[5];
    float* out = (float*)d_out;

    float *Q, *K, *V, *S, *O;
    cudaGetSymbolAddress((void**)&Q, g_Q);
    cudaGetSymbolAddress((void**)&K, g_K);
    cudaGetSymbolAddress((void**)&V, g_V);
    cudaGetSymbolAddress((void**)&S, g_S);
    cudaGetSymbolAddress((void**)&O, g_O);

    const dim3 blk(256);

    // 1) Q/K/V projections: [16384,1024] = [16384,1024] @ [1024,1024]
    {
        dim3 grid(DIM / BN, MTOT / BM, 1);
        sgemm_kernel<false, false><<<grid, blk>>>(x, Wq, nullptr, Q,
                                                  MTOT, DIM, DIM, 0, 0, 0);
        sgemm_kernel<false, false><<<grid, blk>>>(x, Wk, nullptr, K,
                                                  MTOT, DIM, DIM, 0, 0, 0);
        sgemm_kernel<false, false><<<grid, blk>>>(x, Wv, nullptr, V,
                                                  MTOT, DIM, DIM, 0, 0, 0);
    }

    // 2) S = Q @ K^T per batch: [2048,2048] = [2048,1024] @ [2048,1024]^T
    {
        dim3 grid(SEQ / BN, SEQ / BM, BATCH);
        sgemm_kernel<true, false><<<grid, blk>>>(
            Q, K, nullptr, S, SEQ, SEQ, DIM,
            (size_t)SEQ * DIM, (size_t)SEQ * DIM, (size_t)SEQ * SEQ);
    }

    // 3) softmax over rows (scale = D^-0.5 = 1/32)
    softmax_rows_kernel<<<MTOT, blk>>>(S, 0.03125f);

    // 4) O = P @ V per batch: [2048,1024] = [2048,2048] @ [2048,1024]
    {
        dim3 grid(DIM / BN, SEQ / BM, BATCH);
        sgemm_kernel<false, false><<<grid, blk>>>(
            S, V, nullptr, O, SEQ, DIM, SEQ,
            (size_t)SEQ * SEQ, (size_t)SEQ * DIM, (size_t)SEQ * DIM);
    }

    // 5) out = O @ Wp + bp: [16384,1024]
    {
        dim3 grid(DIM / BN, MTOT / BM, 1);
        sgemm_kernel<false, true><<<grid, blk>>>(O, Wp, bp, out,
                                                 MTOT, DIM, DIM, 0, 0, 0);
    }
}

// round 3
// speedup vs baseline: 3.2953x; 3.2953x over previous
#include <cuda_runtime.h>
#include <cuda_bf16.h>
#include <stdint.h>
#include <math.h>

#define BATCH 8
#define SEQ   2048
#define DIM   1024
#define MTOT  (BATCH * SEQ)

// ---------------------------------------------------------------------------
// Static device scratch (allocation-free contract).
// ---------------------------------------------------------------------------
__device__ __align__(256) __nv_bfloat16 g_xh[(size_t)MTOT * DIM];
__device__ __align__(256) __nv_bfloat16 g_xl[(size_t)MTOT * DIM];
__device__ __align__(256) __nv_bfloat16 g_Wth[4][(size_t)DIM * DIM];
__device__ __align__(256) __nv_bfloat16 g_Wtl[4][(size_t)DIM * DIM];
__device__ __align__(256) __nv_bfloat16 g_Qh[(size_t)MTOT * DIM];
__device__ __align__(256) __nv_bfloat16 g_Ql[(size_t)MTOT * DIM];
__device__ __align__(256) __nv_bfloat16 g_Kh[(size_t)MTOT * DIM];
__device__ __align__(256) __nv_bfloat16 g_Kl[(size_t)MTOT * DIM];
__device__ __align__(256) __nv_bfloat16 g_Vh[(size_t)MTOT * DIM];
__device__ __align__(256) __nv_bfloat16 g_Vl[(size_t)MTOT * DIM];
__device__ __align__(256) __nv_bfloat16 g_Vth[(size_t)MTOT * DIM];
__device__ __align__(256) __nv_bfloat16 g_Vtl[(size_t)MTOT * DIM];
__device__ __align__(256) __nv_bfloat16 g_Oh[(size_t)MTOT * DIM];
__device__ __align__(256) __nv_bfloat16 g_Ol[(size_t)MTOT * DIM];
__device__ __align__(256) float          g_S [(size_t)BATCH * SEQ * SEQ];
__device__ __align__(256) __nv_bfloat16 g_Ph[(size_t)BATCH * SEQ * SEQ];
__device__ __align__(256) __nv_bfloat16 g_Pl[(size_t)BATCH * SEQ * SEQ];

// ---------------------------------------------------------------------------
// Helpers (arch-agnostic PTX only: cp.async / ldmatrix / mma.sync)
// ---------------------------------------------------------------------------
__device__ __forceinline__ uint32_t smem_to_u32(const void* smem_ptr) {
    uint32_t addr;
    asm("{ .reg .u64 tmp; cvta.to.shared.u64 tmp, %1; cvt.u32.u64 %0, tmp; }"
        : "=r"(addr) : "l"(smem_ptr));
    return addr;
}
#define SMEM_SWIZZLE_128B(byte_offset) \
    ((byte_offset) ^ (((byte_offset) >> 3) & 0x70))
#define CP_ASYNC_16(dst_u32, src_ptr) \
    asm volatile("cp.async.cg.shared.global [%0], [%1], 16;" \
                 :: "r"(dst_u32), "l"(src_ptr) : "memory")
#define CP_COMMIT() asm volatile("cp.async.commit_group;" ::: "memory")
#define CP_WAIT(n)  asm volatile("cp.async.wait_group %0;" :: "n"(n) : "memory")

#define LDMATRIX_X4(r0, r1, r2, r3, addr) \
    asm volatile("ldmatrix.sync.aligned.m8n8.x4.shared.b16 {%0,%1,%2,%3}, [%4];" \
                 : "=r"(r0), "=r"(r1), "=r"(r2), "=r"(r3) : "r"(addr))

#define MMA_BF16(c, a, b0, b1) \
    asm volatile("mma.sync.aligned.m16n8k16.row.col.f32.bf16.bf16.f32 " \
                 "{%0,%1,%2,%3}, {%4,%5,%6,%7}, {%8,%9}, {%0,%1,%2,%3};" \
                 : "+f"((c)[0]), "+f"((c)[1]), "+f"((c)[2]), "+f"((c)[3]) \
                 : "r"((a)[0]), "r"((a)[1]), "r"((a)[2]), "r"((a)[3]), \
                   "r"(b0), "r"(b1))

// ---------------------------------------------------------------------------
// GEMM: D[M,N] = A@B^T with 3-term bf16 split folded into K_eff = 3K.
//   A_hi/A_lo: [M,K] K-major bf16 ; B_hi/B_lo: [N,K] K-major bf16
// Tile 128x128, BK=64 bf16 (128B rows, SW128), cp.async double buffer,
// 8 warps (4 m x 2 n), warp tile 32x64 via m16n8k16 HMMA.
// EPI: 0 = fp32 out, 1 = fp32 + bias, 2 = split bf16 hi/lo out.
// ---------------------------------------------------------------------------
#define TILE_BYTES 16384            // 128 rows x 128B
#define STAGE_BYTES (2 * TILE_BYTES)
#define SM_TOTAL (2 * STAGE_BYTES)  // 65536

template <int EPI>
__global__ void __launch_bounds__(256)
gemm3_kernel(const __nv_bfloat16* __restrict__ Ah, const __nv_bfloat16* __restrict__ Al,
             const __nv_bfloat16* __restrict__ Bh, const __nv_bfloat16* __restrict__ Bl,
             float* __restrict__ Cf,
             __nv_bfloat16* __restrict__ Ch, __nv_bfloat16* __restrict__ Cl,
             const float* __restrict__ bias,
             int K, int ldC, size_t sA, size_t sB, size_t sC)
{
    extern __shared__ char smem[];
    const uint32_t smem_u = smem_to_u32(smem);
    const int tid = threadIdx.x;
    const int lane = tid & 31;
    const int wid = tid >> 5;
    const int warp_m = wid & 3;          // 4 warps down M (32 rows each)
    const int warp_n = wid >> 2;         // 2 warps across N (64 cols each)
    const int rowBase = blockIdx.y * 128;
    const int colBase = blockIdx.x * 128;
    const size_t zA = (size_t)blockIdx.z * sA;
    const size_t zB = (size_t)blockIdx.z * sB;
    const size_t zC = (size_t)blockIdx.z * sC;

    // loader indices: unit u covers (row = u/8, 16B chunk = u%8); 4 units/thread
    const int ldr_row0 = tid >> 3;       // rows tid/8, +32, +64, +96
    const int ldr_ch   = tid & 7;

    float acc[2][8][4];
#pragma unroll
    for (int i = 0; i < 2; i++)
#pragma unroll
        for (int j = 0; j < 8; j++)
#pragma unroll
            for (int e = 0; e < 4; e++) acc[i][j][e] = 0.0f;

    const int nk = K >> 6;
    const int nIter = 3 * nk;

    auto issue_load = [&](int i, int stage) {
        const int seg = i / nk;
        const int kk = (i - seg * nk) << 6;
        const __nv_bfloat16* As = ((seg == 1) ? Al : Ah) + zA;
        const __nv_bfloat16* Bs = ((seg == 2) ? Bl : Bh) + zB;
        const uint32_t aBase = smem_u + stage * STAGE_BYTES;
        const uint32_t bBase = aBase + TILE_BYTES;
#pragma unroll
        for (int p = 0; p < 4; p++) {
            const int row = ldr_row0 + p * 32;
            const uint32_t soff = SMEM_SWIZZLE_128B((uint32_t)row * 128 + ldr_ch * 16);
            CP_ASYNC_16(aBase + soff,
                        As + (size_t)(rowBase + row) * K + kk + ldr_ch * 8);
            CP_ASYNC_16(bBase + soff,
                        Bs + (size_t)(colBase + row) * K + kk + ldr_ch * 8);
        }
        CP_COMMIT();
    };

    issue_load(0, 0);

    for (int i = 0; i < nIter; i++) {
        const int stage = i & 1;
        if (i + 1 < nIter) {
            issue_load(i + 1, (i + 1) & 1);
            CP_WAIT(1);
        } else {
            CP_WAIT(0);
        }
        __syncthreads();

        const uint32_t aBase = smem_u + stage * STAGE_BYTES;
        const uint32_t bBase = aBase + TILE_BYTES;
#pragma unroll
        for (int ks = 0; ks < 4; ks++) {
            const uint32_t k2 = ks * 32;           // byte offset within 128B row
            uint32_t a[2][4];
#pragma unroll
            for (int fm = 0; fm < 2; fm++) {
                const uint32_t row = warp_m * 32 + fm * 16 + (lane & 15);
                const uint32_t addr = aBase +
                    SMEM_SWIZZLE_128B(row * 128 + k2 + ((lane >> 4) << 4));
                LDMATRIX_X4(a[fm][0], a[fm][1], a[fm][2], a[fm][3], addr);
            }
#pragma unroll
            for (int fn2 = 0; fn2 < 4; fn2++) {
                const uint32_t n = warp_n * 64 + fn2 * 16 + (lane & 7) + ((lane >> 4) << 3);
                const uint32_t addr = bBase +
                    SMEM_SWIZZLE_128B(n * 128 + k2 + (((lane >> 3) & 1) << 4));
                uint32_t b0, b1, b2, b3;
                LDMATRIX_X4(b0, b1, b2, b3, addr);
                MMA_BF16(acc[0][fn2 * 2 + 0], a[0], b0, b1);
                MMA_BF16(acc[0][fn2 * 2 + 1], a[0], b2, b3);
                MMA_BF16(acc[1][fn2 * 2 + 0], a[1], b0, b1);
                MMA_BF16(acc[1][fn2 * 2 + 1], a[1], b2, b3);
            }
        }
        __syncthreads();
    }

    // Epilogue
    const int gid = lane >> 2;
    const int tig = lane & 3;
#pragma unroll
    for (int fm = 0; fm < 2; fm++) {
#pragma unroll
        for (int fn = 0; fn < 8; fn++) {
            const int r0 = rowBase + warp_m * 32 + fm * 16 + gid;
            const int c  = colBase + warp_n * 64 + fn * 8 + tig * 2;
            const float* ac = acc[fm][fn];
            if (EPI == 2) {
                __nv_bfloat162 h0 = __floats2bfloat162_rn(ac[0], ac[1]);
                float2 hf0 = __bfloat1622float2(h0);
                __nv_bfloat162 l0 = __floats2bfloat162_rn(ac[0] - hf0.x, ac[1] - hf0.y);
                __nv_bfloat162 h1 = __floats2bfloat162_rn(ac[2], ac[3]);
                float2 hf1 = __bfloat1622float2(h1);
                __nv_bfloat162 l1 = __floats2bfloat162_rn(ac[2] - hf1.x, ac[3] - hf1.y);
                *(uint32_t*)(Ch + zC + (size_t)r0 * ldC + c)       = *(uint32_t*)&h0;
                *(uint32_t*)(Cl + zC + (size_t)r0 * ldC + c)       = *(uint32_t*)&l0;
                *(uint32_t*)(Ch + zC + (size_t)(r0 + 8) * ldC + c) = *(uint32_t*)&h1;
                *(uint32_t*)(Cl + zC + (size_t)(r0 + 8) * ldC + c) = *(uint32_t*)&l1;
            } else {
                float2 v0 = make_float2(ac[0], ac[1]);
                float2 v1 = make_float2(ac[2], ac[3]);
                if (EPI == 1) {
                    const float b0 = bias[c], b1 = bias[c + 1];
                    v0.x += b0; v0.y += b1;
                    v1.x += b0; v1.y += b1;
                }
                *(float2*)(Cf + zC + (size_t)r0 * ldC + c)       = v0;
                *(float2*)(Cf + zC + (size_t)(r0 + 8) * ldC + c) = v1;
            }
        }
    }
}

// ---------------------------------------------------------------------------
// fp32 -> bf16 hi/lo split (elementwise)
// ---------------------------------------------------------------------------
__global__ void __launch_bounds__(256)
split_fp32_kernel(const float* __restrict__ x,
                  __nv_bfloat16* __restrict__ h, __nv_bfloat16* __restrict__ l)
{
    size_t i = ((size_t)blockIdx.x * 256 + threadIdx.x) * 4;
    float4 v = *(const float4*)(x + i);
    float vv[4] = {v.x, v.y, v.z, v.w};
    __nv_bfloat16 hh[4], ll[4];
#pragma unroll
    for (int j = 0; j < 4; j++) {
        hh[j] = __float2bfloat16(vv[j]);
        ll[j] = __float2bfloat16(vv[j] - __bfloat162float(hh[j]));
    }
    *(uint2*)(h + i) = *(uint2*)hh;
    *(uint2*)(l + i) = *(uint2*)ll;
}

// ---------------------------------------------------------------------------
// Transpose fp32 W [DIM,DIM] -> split bf16 Wt hi/lo (Wt[e,d] = W[d,e])
// ---------------------------------------------------------------------------
__global__ void __launch_bounds__(256)
transW_kernel(const float* __restrict__ W,
              __nv_bfloat16* __restrict__ th, __nv_bfloat16* __restrict__ tl)
{
    __shared__ float t[32][33];
    const int tx = threadIdx.x, ty = threadIdx.y;
    const int x = blockIdx.x * 32 + tx;
    const int y0 = blockIdx.y * 32;
#pragma unroll
    for (int p = 0; p < 4; p++)
        t[ty + 8 * p][tx] = W[(size_t)(y0 + ty + 8 * p) * DIM + x];
    __syncthreads();
    const int ox = blockIdx.y * 32 + tx;
    const int oy0 = blockIdx.x * 32;
#pragma unroll
    for (int p = 0; p < 4; p++) {
        float v = t[tx][ty + 8 * p];
        __nv_bfloat16 h = __float2bfloat16(v);
        __nv_bfloat16 l = __float2bfloat16(v - __bfloat162float(h));
        th[(size_t)(oy0 + ty + 8 * p) * DIM + ox] = h;
        tl[(size_t)(oy0 + ty + 8 * p) * DIM + ox] = l;
    }
}

// ---------------------------------------------------------------------------
// Transpose bf16 pair per batch: V [SEQ,DIM] -> Vt [DIM,SEQ]
// ---------------------------------------------------------------------------
__global__ void __launch_bounds__(256)
transV_kernel(const __nv_bfloat16* __restrict__ ih, const __nv_bfloat16* __restrict__ il,
              __nv_bfloat16* __restrict__ oh, __nv_bfloat16* __restrict__ ol)
{
    __shared__ __nv_bfloat16 t0[32][33];
    __shared__ __nv_bfloat16 t1[32][33];
    const size_t zin = (size_t)blockIdx.z * SEQ * DIM;
    const int tx = threadIdx.x, ty = threadIdx.y;
    const int x = blockIdx.x * 32 + tx;
    const int y0 = blockIdx.y * 32;
#pragma unroll
    for (int p = 0; p < 4; p++) {
        t0[ty + 8 * p][tx] = ih[zin + (size_t)(y0 + ty + 8 * p) * DIM + x];
        t1[ty + 8 * p][tx] = il[zin + (size_t)(y0 + ty + 8 * p) * DIM + x];
    }
    __syncthreads();
    const int ox = blockIdx.y * 32 + tx;
    const int oy0 = blockIdx.x * 32;
#pragma unroll
    for (int p = 0; p < 4; p++) {
        oh[zin + (size_t)(oy0 + ty + 8 * p) * SEQ + ox] = t0[tx][ty + 8 * p];
        ol[zin + (size_t)(oy0 + ty + 8 * p) * SEQ + ox] = t1[tx][ty + 8 * p];
    }
}

// ---------------------------------------------------------------------------
// Row softmax (SEQ=2048 cols) with scale; emits split-bf16 P
// ---------------------------------------------------------------------------
__global__ void __launch_bounds__(256)
softmax_split_kernel(const float* __restrict__ S,
                     __nv_bfloat16* __restrict__ Ph, __nv_bfloat16* __restrict__ Pl,
                     float scale)
{
    const size_t row = blockIdx.x;
    const float* p = S + row * SEQ;
    const int tid = threadIdx.x;

    float vals[8];
    float lmax = -INFINITY;
#pragma unroll
    for (int i = 0; i < 8; i++) {
        float v = p[tid + i * 256] * scale;
        vals[i] = v;
        lmax = fmaxf(lmax, v);
    }
    __shared__ float red[8];
#pragma unroll
    for (int o = 16; o > 0; o >>= 1)
        lmax = fmaxf(lmax, __shfl_xor_sync(0xffffffffu, lmax, o));
    if ((tid & 31) == 0) red[tid >> 5] = lmax;
    __syncthreads();
    float m = red[0];
#pragma unroll
    for (int w = 1; w < 8; w++) m = fmaxf(m, red[w]);
    __syncthreads();

    float lsum = 0.0f;
#pragma unroll
    for (int i = 0; i < 8; i++) {
        vals[i] = expf(vals[i] - m);
        lsum += vals[i];
    }
#pragma unroll
    for (int o = 16; o > 0; o >>= 1)
        lsum += __shfl_xor_sync(0xffffffffu, lsum, o);
    if ((tid & 31) == 0) red[tid >> 5] = lsum;
    __syncthreads();
    float tot = 0.0f;
#pragma unroll
    for (int w = 0; w < 8; w++) tot += red[w];
    const float rinv = 1.0f / tot;

#pragma unroll
    for (int i = 0; i < 8; i++) {
        float v = vals[i] * rinv;
        __nv_bfloat16 h = __float2bfloat16(v);
        __nv_bfloat16 l = __float2bfloat16(v - __bfloat162float(h));
        Ph[row * SEQ + tid + i * 256] = h;
        Pl[row * SEQ + tid + i * 256] = l;
    }
}

// ---------------------------------------------------------------------------
// kernel_launch
// ---------------------------------------------------------------------------
extern "C" void kernel_launch(void* const* d_in, const int* in_sizes, int n_in,
                              void* d_out, int out_size)
{
    (void)in_sizes; (void)n_in; (void)out_size;
    const float* x  = (const float*)d_in[0];
    const float* Wq = (const float*)d_in[1];
    const float* Wk = (const float*)d_in[2];
    const float* Wv = (const float*)d_in[3];
    const float* Wp = (const float*)d_in[4];
    const float* bp = (const float*)d_in[5];
    float* out = (float*)d_out;

    __nv_bfloat16 *xh, *xl, *Wth, *Wtl, *Qh, *Ql, *Kh, *Kl, *Vh, *Vl,
                  *Vth, *Vtl, *Oh, *Ol, *Ph, *Pl;
    float* S;
    cudaGetSymbolAddress((void**)&xh, g_xh);
    cudaGetSymbolAddress((void**)&xl, g_xl);
    cudaGetSymbolAddress((void**)&Wth, g_Wth);
    cudaGetSymbolAddress((void**)&Wtl, g_Wtl);
    cudaGetSymbolAddress((void**)&Qh, g_Qh);
    cudaGetSymbolAddress((void**)&Ql, g_Ql);
    cudaGetSymbolAddress((void**)&Kh, g_Kh);
    cudaGetSymbolAddress((void**)&Kl, g_Kl);
    cudaGetSymbolAddress((void**)&Vh, g_Vh);
    cudaGetSymbolAddress((void**)&Vl, g_Vl);
    cudaGetSymbolAddress((void**)&Vth, g_Vth);
    cudaGetSymbolAddress((void**)&Vtl, g_Vtl);
    cudaGetSymbolAddress((void**)&Oh, g_Oh);
    cudaGetSymbolAddress((void**)&Ol, g_Ol);
    cudaGetSymbolAddress((void**)&S, g_S);
    cudaGetSymbolAddress((void**)&Ph, g_Ph);
    cudaGetSymbolAddress((void**)&Pl, g_Pl);

    const size_t wstep = (size_t)DIM * DIM;

    cudaFuncSetAttribute(gemm3_kernel<0>, cudaFuncAttributeMaxDynamicSharedMemorySize, SM_TOTAL);
    cudaFuncSetAttribute(gemm3_kernel<1>, cudaFuncAttributeMaxDynamicSharedMemorySize, SM_TOTAL);
    cudaFuncSetAttribute(gemm3_kernel<2>, cudaFuncAttributeMaxDynamicSharedMemorySize, SM_TOTAL);

    // 1) split x into bf16 hi/lo
    split_fp32_kernel<<<(size_t)MTOT * DIM / 1024, 256>>>(x, xh, xl);

    // 2) transpose + split the four weight matrices
    {
        dim3 g(DIM / 32, DIM / 32), b(32, 8);
        transW_kernel<<<g, b>>>(Wq, Wth + 0 * wstep, Wtl + 0 * wstep);
        transW_kernel<<<g, b>>>(Wk, Wth + 1 * wstep, Wtl + 1 * wstep);
        transW_kernel<<<g, b>>>(Wv, Wth + 2 * wstep, Wtl + 2 * wstep);
        transW_kernel<<<g, b>>>(Wp, Wth + 3 * wstep, Wtl + 3 * wstep);
    }

    // 3) Q/K/V projections -> split bf16 outputs
    {
        dim3 g(DIM / 128, MTOT / 128, 1);
        gemm3_kernel<2><<<g, 256, SM_TOTAL>>>(xh, xl, Wth + 0 * wstep, Wtl + 0 * wstep,
                                              nullptr, Qh, Ql, nullptr, DIM, DIM, 0, 0, 0);
        gemm3_kernel<2><<<g, 256, SM_TOTAL>>>(xh, xl, Wth + 1 * wstep, Wtl + 1 * wstep,
                                              nullptr, Kh, Kl, nullptr, DIM, DIM, 0, 0, 0);
        gemm3_kernel<2><<<g, 256, SM_TOTAL>>>(xh, xl, Wth + 2 * wstep, Wtl + 2 * wstep,
                                              nullptr, Vh, Vl, nullptr, DIM, DIM, 0, 0, 0);
    }

    // 4) S = Q @ K^T per batch (fp32 out, raw scores)
    {
        dim3 g(SEQ / 128, SEQ / 128, BATCH);
        gemm3_kernel<0><<<g, 256, SM_TOTAL>>>(Qh, Ql, Kh, Kl,
                                              S, nullptr, nullptr, nullptr,
                                              DIM, SEQ,
                                              (size_t)SEQ * DIM, (size_t)SEQ * DIM,
                                              (size_t)SEQ * SEQ);
    }

    // 5) softmax with scale -> split bf16 P
    softmax_split_kernel<<<MTOT, 256>>>(S, Ph, Pl, 0.03125f);

    // 6) transpose V per batch -> Vt [DIM, SEQ]
    {
        dim3 g(DIM / 32, SEQ / 32, BATCH), b(32, 8);
        transV_kernel<<<g, b>>>(Vh, Vl, Vth, Vtl);
    }

    // 7) O = P @ V per batch -> split bf16 O
    {
        dim3 g(DIM / 128, SEQ / 128, BATCH);
        gemm3_kernel<2><<<g, 256, SM_TOTAL>>>(Ph, Pl, Vth, Vtl,
                                              nullptr, Oh, Ol, nullptr,
                                              SEQ, DIM,
                                              (size_t)SEQ * SEQ, (size_t)DIM * SEQ,
                                              (size_t)SEQ * DIM);
    }

    // 8) out = O @ Wp^T + bp (fp32)
    {
        dim3 g(DIM / 128, MTOT / 128, 1);
        gemm3_kernel<1><<<g, 256, SM_TOTAL>>>(Oh, Ol, Wth + 3 * wstep, Wtl + 3 * wstep,
                                              out, nullptr, nullptr, bp,
                                              DIM, DIM, 0, 0, 0);
    }
}